// round 14
// baseline (speedup 1.0000x reference)
#include <cuda_runtime.h>
#include <cuda_bf16.h>

#define BB 8
#define NN 4096
#define KNN 20
#define CAT 320
#define KTILE 2048

typedef unsigned long long ull;

// packed f32x2 helpers (proven in local2_kernel, R7/R13 passes)
#define FMA2(acc, a, b) asm("fma.rn.f32x2 %0, %1, %2, %0;" : "+l"(acc) : "l"(a), "l"(b))
__device__ __forceinline__ ull pack2(float lo, float hi) {
    ull r;
    asm("mov.b64 %0, {%1, %2};" : "=l"(r) : "r"(__float_as_uint(lo)), "r"(__float_as_uint(hi)));
    return r;
}
__device__ __forceinline__ void unpack2(ull v, float& lo, float& hi) {
    unsigned a, b;
    asm("mov.b64 {%0, %1}, %2;" : "=r"(a), "=r"(b) : "l"(v));
    lo = __uint_as_float(a); hi = __uint_as_float(b);
}

// ---------------- scratch (static device globals; no allocation) ----------------
__device__ __align__(16) float d_ptsT[BB * NN * 4];            // [b][n][x,y,z,sq]
__device__ int d_idx[BB * NN * KNN];                           // knn indices
__device__ __align__(16) float d_cat[(size_t)BB * NN * CAT];   // concat features [b][n][320]
__device__ unsigned long long d_keys[BB * 1024];               // packed (val, ~n) for max/argmax
__device__ __align__(16) float4 d_wT4[160 * 512];              // local_w repacked (f32x2 local layer)

// ---------------- prep ----------------
__global__ void prep_points_kernel(const float* __restrict__ pts) {
    int i = blockIdx.x * blockDim.x + threadIdx.x;
    if (i < BB * NN) {
        int b = i / NN, n = i % NN;
        float x = pts[((size_t)b * 3 + 0) * NN + n];
        float y = pts[((size_t)b * 3 + 1) * NN + n];
        float z = pts[((size_t)b * 3 + 2) * NN + n];
        float sq = x * x + y * y + z * z;
        d_ptsT[i * 4 + 0] = x;
        d_ptsT[i * 4 + 1] = y;
        d_ptsT[i * 4 + 2] = z;
        d_ptsT[i * 4 + 3] = sq;
    }
}

__global__ void prep_keys_kernel() {
    int i = blockIdx.x * blockDim.x + threadIdx.x;
    if (i < BB * 1024) d_keys[i] = 0ULL;
}

// local_w [1024][320] -> wT4[c2][t] = (w[t][2c2], w[t+512][2c2], w[t][2c2+1], w[t+512][2c2+1])
__global__ void prep_wT4_kernel(const float* __restrict__ lw) {
    int i = blockIdx.x * blockDim.x + threadIdx.x;  // over 160*512
    if (i < 160 * 512) {
        int c2 = i / 512, t = i % 512;
        d_wT4[i] = make_float4(lw[(size_t)t * 320 + 2 * c2],
                               lw[(size_t)(t + 512) * 320 + 2 * c2],
                               lw[(size_t)t * 320 + 2 * c2 + 1],
                               lw[(size_t)(t + 512) * 320 + 2 * c2 + 1]);
    }
}

// ---------------- kNN: tile candidates through 32 KB static smem (R7-exact) ----------------
__global__ __launch_bounds__(256) void knn_kernel() {
    __shared__ __align__(16) float4 ps[KTILE];  // 32 KB
    int b = blockIdx.y;
    int n = blockIdx.x * blockDim.x + threadIdx.x;

    const float4* src = (const float4*)(d_ptsT) + (size_t)b * NN;
    float4 q = src[n];

    float bd[KNN];
    int bi[KNN];
#pragma unroll
    for (int k = 0; k < KNN; k++) { bd[k] = __int_as_float(0x7f800000); bi[k] = 0x7fffffff; }
    float wv = __int_as_float(0x7f800000);
    int wp = 0;

    for (int tile = 0; tile < NN / KTILE; tile++) {
        __syncthreads();
        for (int t = threadIdx.x; t < KTILE; t += blockDim.x)
            ps[t] = src[tile * KTILE + t];
        __syncthreads();

        const int jbase = tile * KTILE;
        for (int jj = 0; jj < KTILE; jj++) {
            float4 p = ps[jj];
            float dot = q.x * p.x + q.y * p.y + q.z * p.z;
            float dist = q.w + p.w - 2.0f * dot;
            if (dist < wv) {
                int j = jbase + jj;
                bd[wp] = dist; bi[wp] = j;
                float nv = bd[0]; int np = 0; int ni = bi[0];
#pragma unroll
                for (int t = 1; t < KNN; t++) {
                    if (bd[t] > nv || (bd[t] == nv && bi[t] > ni)) { nv = bd[t]; np = t; ni = bi[t]; }
                }
                wv = nv; wp = np;
            }
        }
    }
    int* orow = d_idx + ((size_t)b * NN + n) * KNN;
#pragma unroll
    for (int k = 0; k < KNN; k++) orow[k] = bi[k];
}

// ---------------- EdgeConv layer 1 (CIN=3): R7-exact ----------------
__global__ __launch_bounds__(64) void edge1_kernel(const float* __restrict__ w,
                                                   const float* __restrict__ sc,
                                                   const float* __restrict__ bi) {
    const int CIN = 3, COUT = 64, PPB = 16;
    __shared__ float wd_s[COUT * (CIN + 1)];
    __shared__ __align__(16) float ctr_s[4];
    __shared__ __align__(16) float nb_s[KNN * CIN];

    const int b = blockIdx.y;
    const int n0 = blockIdx.x * PPB;
    const int o = threadIdx.x;

    float w2r[CIN];
#pragma unroll
    for (int c = 0; c < CIN; c++) w2r[c] = w[(size_t)o * 2 * CIN + CIN + c];
    const float sr = sc[o];
    const float br = bi[o];

    for (int t = o; t < COUT * CIN; t += COUT) {
        int oo = t / CIN, c = t % CIN;
        wd_s[oo * (CIN + 1) + c] = w[(size_t)oo * 2 * CIN + c] - w[(size_t)oo * 2 * CIN + CIN + c];
    }
    __syncthreads();

    const float* xin = d_ptsT + (size_t)b * NN * 4;
    float* out = d_cat + (size_t)b * NN * CAT;

    for (int p = 0; p < PPB; p++) {
        const int n = n0 + p;
        const int* idxrow = d_idx + ((size_t)b * NN + n) * KNN;

        for (int t = o; t < KNN * CIN; t += COUT) {
            int k = t / CIN, c = t % CIN;
            nb_s[t] = xin[(size_t)idxrow[k] * 4 + c];
        }
        if (o < CIN) ctr_s[o] = xin[(size_t)n * 4 + o];
        __syncthreads();

        float a = 0.0f;
#pragma unroll
        for (int c = 0; c < CIN; c++) a = fmaf(wd_s[o * (CIN + 1) + c], ctr_s[c], a);

        float m = 0.0f;
#pragma unroll
        for (int k = 0; k < KNN; k++) {
            float acc = a;
#pragma unroll
            for (int c = 0; c < CIN; c++) acc = fmaf(w2r[c], nb_s[k * CIN + c], acc);
            float y = fmaxf(fmaf(sr, acc, br), 0.0f);
            m = fmaxf(m, y);
        }
        out[(size_t)n * CAT + o] = m;
        __syncthreads();
    }
}

// ---------------- EdgeConv layers 2-4 (CIN=64): pipelined + f32x2 point-pair ----------------
// Lane lo = point 2g, lane hi = point 2g+1. Per lane the fp op sequence is
// byte-identical to the R13-passing kernel: wd.ctr (c 0..63), per k channels
// ascending 0..63, fmaf(s,acc,b) -> relu -> max over k ascending.
template <int COUT, int IN_OFF, int OUT_OFF, int PPB>
__global__ __launch_bounds__(COUT) void edge_pair_kernel(const float* __restrict__ w,
                                                         const float* __restrict__ sc,
                                                         const float* __restrict__ bi) {
    constexpr int CIN = 64;
    constexpr int ITEMS = KNN * 16;                  // (k, c4) gather items = 320
    constexpr int NIT = (ITEMS + COUT - 1) / COUT;   // 5 (COUT=64) or 3 (COUT=128)
    __shared__ float wd_s[COUT * (CIN + 1)];
    __shared__ __align__(16) ull nb2[2][KNN * CIN];  // (A,B)-interleaved neighbor tiles
    __shared__ __align__(16) ull ctr2[2][CIN];

    const int b = blockIdx.y;
    const int g0 = blockIdx.x * PPB;  // first pair index
    const int o = threadIdx.x;        // 0..COUT-1

    float w2r[CIN];
#pragma unroll
    for (int c = 0; c < CIN; c++) w2r[c] = w[(size_t)o * 2 * CIN + CIN + c];
    const ull s2 = pack2(sc[o], sc[o]);
    const ull b2 = pack2(bi[o], bi[o]);

    for (int t = o; t < COUT * CIN; t += COUT) {
        int oo = t / CIN, c = t % CIN;
        wd_s[oo * (CIN + 1) + c] = w[(size_t)oo * 2 * CIN + c] - w[(size_t)oo * 2 * CIN + CIN + c];
    }

    const float* xin = d_cat + (size_t)b * NN * CAT + IN_OFF;
    float* out = d_cat + (size_t)b * NN * CAT + OUT_OFF;

    // prologue: gather pair g0 into buffer 0 (interleave A,B per channel)
    {
        const int nA = 2 * g0, nB = nA + 1;
        const int* idxA = d_idx + ((size_t)b * NN + nA) * KNN;
        const int* idxB = d_idx + ((size_t)b * NN + nB) * KNN;
        for (int t = o; t < ITEMS; t += COUT) {
            int k = t >> 4, c4 = t & 15;
            float4 a4 = *(const float4*)(xin + (size_t)idxA[k] * CAT + c4 * 4);
            float4 b4 = *(const float4*)(xin + (size_t)idxB[k] * CAT + c4 * 4);
            ull* dst = &nb2[0][k * CIN + c4 * 4];
            ((float4*)dst)[0] = make_float4(a4.x, b4.x, a4.y, b4.y);
            ((float4*)dst)[1] = make_float4(a4.z, b4.z, a4.w, b4.w);
        }
        if (o < 16) {
            float4 a4 = *(const float4*)(xin + (size_t)nA * CAT + o * 4);
            float4 b4 = *(const float4*)(xin + (size_t)nB * CAT + o * 4);
            ull* dst = &ctr2[0][o * 4];
            ((float4*)dst)[0] = make_float4(a4.x, b4.x, a4.y, b4.y);
            ((float4*)dst)[1] = make_float4(a4.z, b4.z, a4.w, b4.w);
        }
    }
    __syncthreads();

    for (int p = 0; p < PPB; p++) {
        const int cur = p & 1, nxt = cur ^ 1;
        const int nA = 2 * (g0 + p), nB = nA + 1;

        // prefetch next pair into registers (no consumer -> overlaps compute)
        float4 va[NIT], vb[NIT];
        float4 ca, cb;
        if (p + 1 < PPB) {
            const int* idxA2 = d_idx + ((size_t)b * NN + nA + 2) * KNN;
            const int* idxB2 = d_idx + ((size_t)b * NN + nA + 3) * KNN;
#pragma unroll
            for (int i = 0; i < NIT; i++) {
                int t = o + i * COUT;
                if (t < ITEMS) {
                    int k = t >> 4, c4 = t & 15;
                    va[i] = *(const float4*)(xin + (size_t)idxA2[k] * CAT + c4 * 4);
                    vb[i] = *(const float4*)(xin + (size_t)idxB2[k] * CAT + c4 * 4);
                }
            }
            if (o < 16) {
                ca = *(const float4*)(xin + (size_t)(nA + 2) * CAT + o * 4);
                cb = *(const float4*)(xin + (size_t)(nA + 3) * CAT + o * 4);
            }
        }

        // ctr base, scalar per lane (c = 0..63, R13-exact order)
        float aA = 0.0f, aB = 0.0f;
#pragma unroll
        for (int c = 0; c < CIN; c++) {
            float wd = wd_s[o * (CIN + 1) + c];
            float cA, cB;
            unpack2(ctr2[cur][c], cA, cB);
            aA = fmaf(wd, cA, aA);
            aB = fmaf(wd, cB, aB);
        }
        const ull base2 = pack2(aA, aB);

        ull accs[KNN];
#pragma unroll
        for (int k = 0; k < KNN; k++) accs[k] = base2;

        // channels in 8 chunks of 8, ascending; per k channels ascend 0..63
#pragma unroll
        for (int cc = 0; cc < 8; cc++) {
            ull wp[8];
#pragma unroll
            for (int j = 0; j < 8; j++) wp[j] = pack2(w2r[cc * 8 + j], w2r[cc * 8 + j]);
#pragma unroll
            for (int k = 0; k < KNN; k++) {
                const ulonglong2* row = (const ulonglong2*)(nb2[cur] + k * CIN + cc * 8);
                ulonglong2 v0 = row[0], v1 = row[1], v2 = row[2], v3 = row[3];
                FMA2(accs[k], wp[0], v0.x);
                FMA2(accs[k], wp[1], v0.y);
                FMA2(accs[k], wp[2], v1.x);
                FMA2(accs[k], wp[3], v1.y);
                FMA2(accs[k], wp[4], v2.x);
                FMA2(accs[k], wp[5], v2.y);
                FMA2(accs[k], wp[6], v3.x);
                FMA2(accs[k], wp[7], v3.y);
            }
        }

        float mA = 0.0f, mB = 0.0f;
#pragma unroll
        for (int k = 0; k < KNN; k++) {
            ull y = b2;
            FMA2(y, s2, accs[k]);
            float yA, yB;
            unpack2(y, yA, yB);
            mA = fmaxf(mA, yA);
            mB = fmaxf(mB, yB);
        }
        out[(size_t)nA * CAT + o] = mA;
        out[(size_t)nB * CAT + o] = mB;

        // stage prefetched pair into the other buffer
        if (p + 1 < PPB) {
#pragma unroll
            for (int i = 0; i < NIT; i++) {
                int t = o + i * COUT;
                if (t < ITEMS) {
                    int k = t >> 4, c4 = t & 15;
                    ull* dst = &nb2[nxt][k * CIN + c4 * 4];
                    ((float4*)dst)[0] = make_float4(va[i].x, vb[i].x, va[i].y, vb[i].y);
                    ((float4*)dst)[1] = make_float4(va[i].z, vb[i].z, va[i].w, vb[i].w);
                }
            }
            if (o < 16) {
                ull* dst = &ctr2[nxt][o * 4];
                ((float4*)dst)[0] = make_float4(ca.x, cb.x, ca.y, cb.y);
                ((float4*)dst)[1] = make_float4(ca.z, cb.z, ca.w, cb.w);
            }
        }
        __syncthreads();
    }
}

// ---------------- local 1024x320 pointwise MLP + global max/argmax (f32x2, proven) ----------------
__global__ __launch_bounds__(512, 1) void local2_kernel(const float* __restrict__ ls,
                                                        const float* __restrict__ lb) {
    __shared__ __align__(16) ull xs2[16][CAT];  // 40 KB: interleaved point-pair features
    const int b = blockIdx.y;
    const int n0 = blockIdx.x * 32;
    const int t = threadIdx.x;

    const float* cat = d_cat + (size_t)b * NN * CAT;
    for (int item = t; item < 16 * 80; item += 512) {
        int p2 = item / 80, c4 = item % 80;
        int A = n0 + 2 * p2;
        float4 a4 = *(const float4*)(cat + (size_t)A * CAT + c4 * 4);
        float4 b4 = *(const float4*)(cat + (size_t)(A + 1) * CAT + c4 * 4);
        ull* dst = &xs2[p2][c4 * 4];
        *(float4*)(dst)     = make_float4(a4.x, b4.x, a4.y, b4.y);
        *(float4*)(dst + 2) = make_float4(a4.z, b4.z, a4.w, b4.w);
    }
    __syncthreads();

    ull acc[2][16];
#pragma unroll
    for (int j = 0; j < 2; j++)
#pragma unroll
        for (int p = 0; p < 16; p++) acc[j][p] = 0ULL;

    for (int c2 = 0; c2 < 160; c2++) {
        float4 wv = d_wT4[c2 * 512 + t];
        ull w00 = pack2(wv.x, wv.x);
        ull w10 = pack2(wv.y, wv.y);
        ull w01 = pack2(wv.z, wv.z);
        ull w11 = pack2(wv.w, wv.w);
#pragma unroll
        for (int p = 0; p < 16; p++) {
            ulonglong2 x = *(const ulonglong2*)&xs2[p][2 * c2];
            FMA2(acc[0][p], w00, x.x);
            FMA2(acc[0][p], w01, x.y);
            FMA2(acc[1][p], w10, x.x);
            FMA2(acc[1][p], w11, x.y);
        }
    }

#pragma unroll
    for (int j = 0; j < 2; j++) {
        int och = t + j * 512;
        float sv = ls[och], bv = lb[och];
        float best = -1.0f;
        int bn = n0;
#pragma unroll
        for (int p = 0; p < 16; p++) {
            float vA, vB;
            unpack2(acc[j][p], vA, vB);
            float a = fmaxf(fmaf(sv, vA, bv), 0.0f);
            float c = fmaxf(fmaf(sv, vB, bv), 0.0f);
            if (a > best) { best = a; bn = n0 + 2 * p; }
            if (c > best) { best = c; bn = n0 + 2 * p + 1; }
        }
        unsigned long long key =
            ((unsigned long long)__float_as_uint(best) << 32) |
            (unsigned long long)(0xFFFFFFFFu - (unsigned)bn);
        atomicMax(&d_keys[b * 1024 + och], key);
    }
}

// ---------------- head: decode glob + indices, 1024->512->256 ----------------
__global__ __launch_bounds__(512) void head_kernel(const float* __restrict__ gw0,
                                                   const float* __restrict__ gs0,
                                                   const float* __restrict__ gb0,
                                                   const float* __restrict__ gw1,
                                                   const float* __restrict__ gs1,
                                                   const float* __restrict__ gb1,
                                                   float* __restrict__ outp) {
    __shared__ float glob[1024];
    __shared__ float hb[512];
    const int b = blockIdx.x;
    const int t = threadIdx.x;

    for (int i = t; i < 1024; i += 512) {
        unsigned long long k = d_keys[b * 1024 + i];
        glob[i] = __uint_as_float((unsigned)(k >> 32));
        outp[2048 + b * 1024 + i] = (float)(0xFFFFFFFFu - (unsigned)(k & 0xFFFFFFFFull));
    }
    __syncthreads();

    {
        float acc = 0.0f;
        const float* wr = gw0 + (size_t)t * 1024;
        for (int c = 0; c < 1024; c++) acc = fmaf(wr[c], glob[c], acc);
        hb[t] = fmaxf(fmaf(gs0[t], acc, gb0[t]), 0.0f);
    }
    __syncthreads();

    if (t < 256) {
        float acc = 0.0f;
        const float* wr = gw1 + (size_t)t * 512;
        for (int c = 0; c < 512; c++) acc = fmaf(wr[c], hb[c], acc);
        outp[b * 256 + t] = fmaxf(fmaf(gs1[t], acc, gb1[t]), 0.0f);
    }
}

// ---------------- launch ----------------
extern "C" void kernel_launch(void* const* d_in, const int* in_sizes, int n_in,
                              void* d_out, int out_size) {
    const float* pts    = (const float*)d_in[0];
    const float* ec_w0  = (const float*)d_in[1];
    const float* ec_s0  = (const float*)d_in[2];
    const float* ec_b0  = (const float*)d_in[3];
    const float* ec_w1  = (const float*)d_in[4];
    const float* ec_s1  = (const float*)d_in[5];
    const float* ec_b1  = (const float*)d_in[6];
    const float* ec_w2  = (const float*)d_in[7];
    const float* ec_s2  = (const float*)d_in[8];
    const float* ec_b2  = (const float*)d_in[9];
    const float* ec_w3  = (const float*)d_in[10];
    const float* ec_s3  = (const float*)d_in[11];
    const float* ec_b3  = (const float*)d_in[12];
    const float* localw = (const float*)d_in[13];
    const float* locals = (const float*)d_in[14];
    const float* localb = (const float*)d_in[15];
    const float* g_w0   = (const float*)d_in[16];
    const float* g_s0   = (const float*)d_in[17];
    const float* g_b0   = (const float*)d_in[18];
    const float* g_w1   = (const float*)d_in[19];
    const float* g_s1   = (const float*)d_in[20];
    const float* g_b1   = (const float*)d_in[21];
    float* outp = (float*)d_out;

    prep_points_kernel<<<(BB * NN + 255) / 256, 256>>>(pts);
    prep_keys_kernel<<<(BB * 1024 + 255) / 256, 256>>>();
    prep_wT4_kernel<<<(160 * 512 + 255) / 256, 256>>>(localw);

    knn_kernel<<<dim3(NN / 256, BB), 256>>>();   // 4th launch -> ncu capture slot

    edge1_kernel<<<dim3(NN / 16, BB), 64>>>(ec_w0, ec_s0, ec_b0);

    // paired + pipelined CIN=64 layers: 8 pairs (16 points) per block
    edge_pair_kernel<64, 0, 64, 8><<<dim3(NN / 16, BB), 64>>>(ec_w1, ec_s1, ec_b1);
    edge_pair_kernel<64, 64, 128, 8><<<dim3(NN / 16, BB), 64>>>(ec_w2, ec_s2, ec_b2);
    edge_pair_kernel<128, 128, 192, 8><<<dim3(NN / 16, BB), 128>>>(ec_w3, ec_s3, ec_b3);

    local2_kernel<<<dim3(NN / 32, BB), 512>>>(locals, localb);

    head_kernel<<<BB, 512>>>(g_w0, g_s0, g_b0, g_w1, g_s1, g_b1, outp);
}

// round 16
// speedup vs baseline: 1.0692x; 1.0692x over previous
#include <cuda_runtime.h>
#include <cuda_bf16.h>

#define BB 8
#define NN 4096
#define KNN 20
#define CAT 320
#define KTILE 2048

typedef unsigned long long ull;

// packed f32x2 helpers (proven in local2_kernel, R7/R13 passes)
#define FMA2(acc, a, b) asm("fma.rn.f32x2 %0, %1, %2, %0;" : "+l"(acc) : "l"(a), "l"(b))
__device__ __forceinline__ ull pack2(float lo, float hi) {
    ull r;
    asm("mov.b64 %0, {%1, %2};" : "=l"(r) : "r"(__float_as_uint(lo)), "r"(__float_as_uint(hi)));
    return r;
}
__device__ __forceinline__ void unpack2(ull v, float& lo, float& hi) {
    unsigned a, b;
    asm("mov.b64 {%0, %1}, %2;" : "=r"(a), "=r"(b) : "l"(v));
    lo = __uint_as_float(a); hi = __uint_as_float(b);
}

// ---------------- scratch (static device globals; no allocation) ----------------
__device__ __align__(16) float d_ptsT[BB * NN * 4];            // [b][n][x,y,z,sq]
__device__ int d_idx[BB * NN * KNN];                           // knn indices
__device__ __align__(16) float d_cat[(size_t)BB * NN * CAT];   // concat features [b][n][320]
__device__ unsigned long long d_keys[BB * 1024];               // packed (val, ~n) for max/argmax
__device__ __align__(16) float4 d_wT4[160 * 512];              // local_w repacked (f32x2 local layer)

// ---------------- prep ----------------
__global__ void prep_points_kernel(const float* __restrict__ pts) {
    int i = blockIdx.x * blockDim.x + threadIdx.x;
    if (i < BB * NN) {
        int b = i / NN, n = i % NN;
        float x = pts[((size_t)b * 3 + 0) * NN + n];
        float y = pts[((size_t)b * 3 + 1) * NN + n];
        float z = pts[((size_t)b * 3 + 2) * NN + n];
        float sq = x * x + y * y + z * z;
        d_ptsT[i * 4 + 0] = x;
        d_ptsT[i * 4 + 1] = y;
        d_ptsT[i * 4 + 2] = z;
        d_ptsT[i * 4 + 3] = sq;
    }
}

__global__ void prep_keys_kernel() {
    int i = blockIdx.x * blockDim.x + threadIdx.x;
    if (i < BB * 1024) d_keys[i] = 0ULL;
}

// local_w [1024][320] -> wT4[c2][t] = (w[t][2c2], w[t+512][2c2], w[t][2c2+1], w[t+512][2c2+1])
__global__ void prep_wT4_kernel(const float* __restrict__ lw) {
    int i = blockIdx.x * blockDim.x + threadIdx.x;  // over 160*512
    if (i < 160 * 512) {
        int c2 = i / 512, t = i % 512;
        d_wT4[i] = make_float4(lw[(size_t)t * 320 + 2 * c2],
                               lw[(size_t)(t + 512) * 320 + 2 * c2],
                               lw[(size_t)t * 320 + 2 * c2 + 1],
                               lw[(size_t)(t + 512) * 320 + 2 * c2 + 1]);
    }
}

// ---------------- kNN: 4 threads per point, stride-4 candidate split + shfl merge ----------------
// The maintained list is always the 20 lex-smallest (dist, idx) pairs seen
// (order-independent); the merged set is exactly the R7-passing kernel's set.
__global__ __launch_bounds__(256) void knn_kernel() {
    __shared__ __align__(16) float4 ps[KTILE];  // 32 KB
    const int b = blockIdx.y;
    const int t = threadIdx.x;
    const int s = t & 3;                 // sub-scanner 0..3
    const int n = blockIdx.x * 64 + (t >> 2);

    const float4* src = (const float4*)(d_ptsT) + (size_t)b * NN;
    float4 q = src[n];

    float bd[KNN];
    int bi[KNN];
#pragma unroll
    for (int k = 0; k < KNN; k++) { bd[k] = __int_as_float(0x7f800000); bi[k] = 0x7fffffff; }
    float wv = __int_as_float(0x7f800000);  // lex-largest (worst) value in list
    int wi = 0x7fffffff;                    // its index
    int wp = 0;                             // its position

    for (int tile = 0; tile < NN / KTILE; tile++) {
        __syncthreads();
        for (int i = t; i < KTILE; i += 256)
            ps[i] = src[tile * KTILE + i];
        __syncthreads();

        const int jbase = tile * KTILE;
        for (int i = 0; i < KTILE / 4; i++) {
            int jj = 4 * i + s;
            float4 p = ps[jj];
            float dot = q.x * p.x + q.y * p.y + q.z * p.z;
            float dist = q.w + p.w - 2.0f * dot;
            int j = jbase + jj;
            if (dist < wv || (dist == wv && j < wi)) {   // tie clause never fires in-scan (j ascending)
                bd[wp] = dist; bi[wp] = j;
                float nv = bd[0]; int np = 0; int ni = bi[0];
#pragma unroll
                for (int u = 1; u < KNN; u++) {
                    if (bd[u] > nv || (bd[u] == nv && bi[u] > ni)) { nv = bd[u]; np = u; ni = bi[u]; }
                }
                wv = nv; wp = np; wi = ni;
            }
        }
    }

    // merge the 4 sub-lists of each point into lane s==0 via warp shuffles
    const unsigned FULL = 0xFFFFFFFFu;
    const int lane = t & 31;
    const int base = lane & ~3;
    for (int srcl = 1; srcl < 4; srcl++) {
#pragma unroll
        for (int k = 0; k < KNN; k++) {
            float d = __shfl_sync(FULL, bd[k], base + srcl);
            int j = __shfl_sync(FULL, bi[k], base + srcl);
            if (s == 0) {
                if (d < wv || (d == wv && j < wi)) {
                    bd[wp] = d; bi[wp] = j;
                    float nv = bd[0]; int np = 0; int ni = bi[0];
#pragma unroll
                    for (int u = 1; u < KNN; u++) {
                        if (bd[u] > nv || (bd[u] == nv && bi[u] > ni)) { nv = bd[u]; np = u; ni = bi[u]; }
                    }
                    wv = nv; wp = np; wi = ni;
                }
            }
        }
    }

    if (s == 0) {
        int* orow = d_idx + ((size_t)b * NN + n) * KNN;
#pragma unroll
        for (int k = 0; k < KNN; k++) orow[k] = bi[k];
    }
}

// ---------------- EdgeConv layer 1 (CIN=3): R7-exact ----------------
__global__ __launch_bounds__(64) void edge1_kernel(const float* __restrict__ w,
                                                   const float* __restrict__ sc,
                                                   const float* __restrict__ bi) {
    const int CIN = 3, COUT = 64, PPB = 16;
    __shared__ float wd_s[COUT * (CIN + 1)];
    __shared__ __align__(16) float ctr_s[4];
    __shared__ __align__(16) float nb_s[KNN * CIN];

    const int b = blockIdx.y;
    const int n0 = blockIdx.x * PPB;
    const int o = threadIdx.x;

    float w2r[CIN];
#pragma unroll
    for (int c = 0; c < CIN; c++) w2r[c] = w[(size_t)o * 2 * CIN + CIN + c];
    const float sr = sc[o];
    const float br = bi[o];

    for (int t = o; t < COUT * CIN; t += COUT) {
        int oo = t / CIN, c = t % CIN;
        wd_s[oo * (CIN + 1) + c] = w[(size_t)oo * 2 * CIN + c] - w[(size_t)oo * 2 * CIN + CIN + c];
    }
    __syncthreads();

    const float* xin = d_ptsT + (size_t)b * NN * 4;
    float* out = d_cat + (size_t)b * NN * CAT;

    for (int p = 0; p < PPB; p++) {
        const int n = n0 + p;
        const int* idxrow = d_idx + ((size_t)b * NN + n) * KNN;

        for (int t = o; t < KNN * CIN; t += COUT) {
            int k = t / CIN, c = t % CIN;
            nb_s[t] = xin[(size_t)idxrow[k] * 4 + c];
        }
        if (o < CIN) ctr_s[o] = xin[(size_t)n * 4 + o];
        __syncthreads();

        float a = 0.0f;
#pragma unroll
        for (int c = 0; c < CIN; c++) a = fmaf(wd_s[o * (CIN + 1) + c], ctr_s[c], a);

        float m = 0.0f;
#pragma unroll
        for (int k = 0; k < KNN; k++) {
            float acc = a;
#pragma unroll
            for (int c = 0; c < CIN; c++) acc = fmaf(w2r[c], nb_s[k * CIN + c], acc);
            float y = fmaxf(fmaf(sr, acc, br), 0.0f);
            m = fmaxf(m, y);
        }
        out[(size_t)n * CAT + o] = m;
        __syncthreads();
    }
}

// ---------------- EdgeConv layers 2-4 (CIN=64): pipelined + f32x2 point-pair ----------------
// Lane lo = point 2g, lane hi = point 2g+1. Per lane the fp op sequence is
// byte-identical to the R13-passing kernel.
template <int COUT, int IN_OFF, int OUT_OFF, int PPB>
__global__ __launch_bounds__(COUT) void edge_pair_kernel(const float* __restrict__ w,
                                                         const float* __restrict__ sc,
                                                         const float* __restrict__ bi) {
    constexpr int CIN = 64;
    constexpr int ITEMS = KNN * 16;                  // (k, c4) gather items = 320
    constexpr int NIT = (ITEMS + COUT - 1) / COUT;   // 5 (COUT=64) or 3 (COUT=128)
    __shared__ float wd_s[COUT * (CIN + 1)];
    __shared__ __align__(16) ull nb2[2][KNN * CIN];  // (A,B)-interleaved neighbor tiles
    __shared__ __align__(16) ull ctr2[2][CIN];

    const int b = blockIdx.y;
    const int g0 = blockIdx.x * PPB;  // first pair index
    const int o = threadIdx.x;        // 0..COUT-1

    float w2r[CIN];
#pragma unroll
    for (int c = 0; c < CIN; c++) w2r[c] = w[(size_t)o * 2 * CIN + CIN + c];
    const ull s2 = pack2(sc[o], sc[o]);
    const ull b2 = pack2(bi[o], bi[o]);

    for (int t = o; t < COUT * CIN; t += COUT) {
        int oo = t / CIN, c = t % CIN;
        wd_s[oo * (CIN + 1) + c] = w[(size_t)oo * 2 * CIN + c] - w[(size_t)oo * 2 * CIN + CIN + c];
    }

    const float* xin = d_cat + (size_t)b * NN * CAT + IN_OFF;
    float* out = d_cat + (size_t)b * NN * CAT + OUT_OFF;

    // prologue: gather pair g0 into buffer 0 (interleave A,B per channel)
    {
        const int nA = 2 * g0, nB = nA + 1;
        const int* idxA = d_idx + ((size_t)b * NN + nA) * KNN;
        const int* idxB = d_idx + ((size_t)b * NN + nB) * KNN;
        for (int t = o; t < ITEMS; t += COUT) {
            int k = t >> 4, c4 = t & 15;
            float4 a4 = *(const float4*)(xin + (size_t)idxA[k] * CAT + c4 * 4);
            float4 b4 = *(const float4*)(xin + (size_t)idxB[k] * CAT + c4 * 4);
            ull* dst = &nb2[0][k * CIN + c4 * 4];
            ((float4*)dst)[0] = make_float4(a4.x, b4.x, a4.y, b4.y);
            ((float4*)dst)[1] = make_float4(a4.z, b4.z, a4.w, b4.w);
        }
        if (o < 16) {
            float4 a4 = *(const float4*)(xin + (size_t)nA * CAT + o * 4);
            float4 b4 = *(const float4*)(xin + (size_t)nB * CAT + o * 4);
            ull* dst = &ctr2[0][o * 4];
            ((float4*)dst)[0] = make_float4(a4.x, b4.x, a4.y, b4.y);
            ((float4*)dst)[1] = make_float4(a4.z, b4.z, a4.w, b4.w);
        }
    }
    __syncthreads();

    for (int p = 0; p < PPB; p++) {
        const int cur = p & 1, nxt = cur ^ 1;
        const int nA = 2 * (g0 + p), nB = nA + 1;

        // prefetch next pair into registers (no consumer -> overlaps compute)
        float4 va[NIT], vb[NIT];
        float4 ca, cb;
        if (p + 1 < PPB) {
            const int* idxA2 = d_idx + ((size_t)b * NN + nA + 2) * KNN;
            const int* idxB2 = d_idx + ((size_t)b * NN + nA + 3) * KNN;
#pragma unroll
            for (int i = 0; i < NIT; i++) {
                int t = o + i * COUT;
                if (t < ITEMS) {
                    int k = t >> 4, c4 = t & 15;
                    va[i] = *(const float4*)(xin + (size_t)idxA2[k] * CAT + c4 * 4);
                    vb[i] = *(const float4*)(xin + (size_t)idxB2[k] * CAT + c4 * 4);
                }
            }
            if (o < 16) {
                ca = *(const float4*)(xin + (size_t)(nA + 2) * CAT + o * 4);
                cb = *(const float4*)(xin + (size_t)(nA + 3) * CAT + o * 4);
            }
        }

        // ctr base, scalar per lane (c = 0..63, R13-exact order)
        float aA = 0.0f, aB = 0.0f;
#pragma unroll
        for (int c = 0; c < CIN; c++) {
            float wd = wd_s[o * (CIN + 1) + c];
            float cA, cB;
            unpack2(ctr2[cur][c], cA, cB);
            aA = fmaf(wd, cA, aA);
            aB = fmaf(wd, cB, aB);
        }
        const ull base2 = pack2(aA, aB);

        ull accs[KNN];
#pragma unroll
        for (int k = 0; k < KNN; k++) accs[k] = base2;

        // channels in 8 chunks of 8, ascending; per k channels ascend 0..63
#pragma unroll
        for (int cc = 0; cc < 8; cc++) {
            ull wp[8];
#pragma unroll
            for (int j = 0; j < 8; j++) wp[j] = pack2(w2r[cc * 8 + j], w2r[cc * 8 + j]);
#pragma unroll
            for (int k = 0; k < KNN; k++) {
                const ulonglong2* row = (const ulonglong2*)(nb2[cur] + k * CIN + cc * 8);
                ulonglong2 v0 = row[0], v1 = row[1], v2 = row[2], v3 = row[3];
                FMA2(accs[k], wp[0], v0.x);
                FMA2(accs[k], wp[1], v0.y);
                FMA2(accs[k], wp[2], v1.x);
                FMA2(accs[k], wp[3], v1.y);
                FMA2(accs[k], wp[4], v2.x);
                FMA2(accs[k], wp[5], v2.y);
                FMA2(accs[k], wp[6], v3.x);
                FMA2(accs[k], wp[7], v3.y);
            }
        }

        float mA = 0.0f, mB = 0.0f;
#pragma unroll
        for (int k = 0; k < KNN; k++) {
            ull y = b2;
            FMA2(y, s2, accs[k]);
            float yA, yB;
            unpack2(y, yA, yB);
            mA = fmaxf(mA, yA);
            mB = fmaxf(mB, yB);
        }
        out[(size_t)nA * CAT + o] = mA;
        out[(size_t)nB * CAT + o] = mB;

        // stage prefetched pair into the other buffer
        if (p + 1 < PPB) {
#pragma unroll
            for (int i = 0; i < NIT; i++) {
                int t = o + i * COUT;
                if (t < ITEMS) {
                    int k = t >> 4, c4 = t & 15;
                    ull* dst = &nb2[nxt][k * CIN + c4 * 4];
                    ((float4*)dst)[0] = make_float4(va[i].x, vb[i].x, va[i].y, vb[i].y);
                    ((float4*)dst)[1] = make_float4(va[i].z, vb[i].z, va[i].w, vb[i].w);
                }
            }
            if (o < 16) {
                ull* dst = &ctr2[nxt][o * 4];
                ((float4*)dst)[0] = make_float4(ca.x, cb.x, ca.y, cb.y);
                ((float4*)dst)[1] = make_float4(ca.z, cb.z, ca.w, cb.w);
            }
        }
        __syncthreads();
    }
}

// ---------------- local 1024x320 pointwise MLP + global max/argmax (f32x2, proven) ----------------
__global__ __launch_bounds__(512, 1) void local2_kernel(const float* __restrict__ ls,
                                                        const float* __restrict__ lb) {
    __shared__ __align__(16) ull xs2[16][CAT];  // 40 KB: interleaved point-pair features
    const int b = blockIdx.y;
    const int n0 = blockIdx.x * 32;
    const int t = threadIdx.x;

    const float* cat = d_cat + (size_t)b * NN * CAT;
    for (int item = t; item < 16 * 80; item += 512) {
        int p2 = item / 80, c4 = item % 80;
        int A = n0 + 2 * p2;
        float4 a4 = *(const float4*)(cat + (size_t)A * CAT + c4 * 4);
        float4 b4 = *(const float4*)(cat + (size_t)(A + 1) * CAT + c4 * 4);
        ull* dst = &xs2[p2][c4 * 4];
        *(float4*)(dst)     = make_float4(a4.x, b4.x, a4.y, b4.y);
        *(float4*)(dst + 2) = make_float4(a4.z, b4.z, a4.w, b4.w);
    }
    __syncthreads();

    ull acc[2][16];
#pragma unroll
    for (int j = 0; j < 2; j++)
#pragma unroll
        for (int p = 0; p < 16; p++) acc[j][p] = 0ULL;

    for (int c2 = 0; c2 < 160; c2++) {
        float4 wv = d_wT4[c2 * 512 + t];
        ull w00 = pack2(wv.x, wv.x);
        ull w10 = pack2(wv.y, wv.y);
        ull w01 = pack2(wv.z, wv.z);
        ull w11 = pack2(wv.w, wv.w);
#pragma unroll
        for (int p = 0; p < 16; p++) {
            ulonglong2 x = *(const ulonglong2*)&xs2[p][2 * c2];
            FMA2(acc[0][p], w00, x.x);
            FMA2(acc[0][p], w01, x.y);
            FMA2(acc[1][p], w10, x.x);
            FMA2(acc[1][p], w11, x.y);
        }
    }

#pragma unroll
    for (int j = 0; j < 2; j++) {
        int och = t + j * 512;
        float sv = ls[och], bv = lb[och];
        float best = -1.0f;
        int bn = n0;
#pragma unroll
        for (int p = 0; p < 16; p++) {
            float vA, vB;
            unpack2(acc[j][p], vA, vB);
            float a = fmaxf(fmaf(sv, vA, bv), 0.0f);
            float c = fmaxf(fmaf(sv, vB, bv), 0.0f);
            if (a > best) { best = a; bn = n0 + 2 * p; }
            if (c > best) { best = c; bn = n0 + 2 * p + 1; }
        }
        unsigned long long key =
            ((unsigned long long)__float_as_uint(best) << 32) |
            (unsigned long long)(0xFFFFFFFFu - (unsigned)bn);
        atomicMax(&d_keys[b * 1024 + och], key);
    }
}

// ---------------- head: decode glob + indices, 1024->512->256 ----------------
__global__ __launch_bounds__(512) void head_kernel(const float* __restrict__ gw0,
                                                   const float* __restrict__ gs0,
                                                   const float* __restrict__ gb0,
                                                   const float* __restrict__ gw1,
                                                   const float* __restrict__ gs1,
                                                   const float* __restrict__ gb1,
                                                   float* __restrict__ outp) {
    __shared__ float glob[1024];
    __shared__ float hb[512];
    const int b = blockIdx.x;
    const int t = threadIdx.x;

    for (int i = t; i < 1024; i += 512) {
        unsigned long long k = d_keys[b * 1024 + i];
        glob[i] = __uint_as_float((unsigned)(k >> 32));
        outp[2048 + b * 1024 + i] = (float)(0xFFFFFFFFu - (unsigned)(k & 0xFFFFFFFFull));
    }
    __syncthreads();

    {
        float acc = 0.0f;
        const float* wr = gw0 + (size_t)t * 1024;
        for (int c = 0; c < 1024; c++) acc = fmaf(wr[c], glob[c], acc);
        hb[t] = fmaxf(fmaf(gs0[t], acc, gb0[t]), 0.0f);
    }
    __syncthreads();

    if (t < 256) {
        float acc = 0.0f;
        const float* wr = gw1 + (size_t)t * 512;
        for (int c = 0; c < 512; c++) acc = fmaf(wr[c], hb[c], acc);
        outp[b * 256 + t] = fmaxf(fmaf(gs1[t], acc, gb1[t]), 0.0f);
    }
}

// ---------------- launch ----------------
extern "C" void kernel_launch(void* const* d_in, const int* in_sizes, int n_in,
                              void* d_out, int out_size) {
    const float* pts    = (const float*)d_in[0];
    const float* ec_w0  = (const float*)d_in[1];
    const float* ec_s0  = (const float*)d_in[2];
    const float* ec_b0  = (const float*)d_in[3];
    const float* ec_w1  = (const float*)d_in[4];
    const float* ec_s1  = (const float*)d_in[5];
    const float* ec_b1  = (const float*)d_in[6];
    const float* ec_w2  = (const float*)d_in[7];
    const float* ec_s2  = (const float*)d_in[8];
    const float* ec_b2  = (const float*)d_in[9];
    const float* ec_w3  = (const float*)d_in[10];
    const float* ec_s3  = (const float*)d_in[11];
    const float* ec_b3  = (const float*)d_in[12];
    const float* localw = (const float*)d_in[13];
    const float* locals = (const float*)d_in[14];
    const float* localb = (const float*)d_in[15];
    const float* g_w0   = (const float*)d_in[16];
    const float* g_s0   = (const float*)d_in[17];
    const float* g_b0   = (const float*)d_in[18];
    const float* g_w1   = (const float*)d_in[19];
    const float* g_s1   = (const float*)d_in[20];
    const float* g_b1   = (const float*)d_in[21];
    float* outp = (float*)d_out;

    prep_points_kernel<<<(BB * NN + 255) / 256, 256>>>(pts);

    knn_kernel<<<dim3(NN / 64, BB), 256>>>();

    edge1_kernel<<<dim3(NN / 16, BB), 64>>>(ec_w0, ec_s0, ec_b0);

    // 4th launch -> ncu capture slot: measure the paired edge kernel
    edge_pair_kernel<64, 0, 64, 8><<<dim3(NN / 16, BB), 64>>>(ec_w1, ec_s1, ec_b1);

    prep_keys_kernel<<<(BB * 1024 + 255) / 256, 256>>>();
    prep_wT4_kernel<<<(160 * 512 + 255) / 256, 256>>>(localw);

    edge_pair_kernel<64, 64, 128, 8><<<dim3(NN / 16, BB), 64>>>(ec_w2, ec_s2, ec_b2);
    edge_pair_kernel<128, 128, 192, 8><<<dim3(NN / 16, BB), 128>>>(ec_w3, ec_s3, ec_b3);

    local2_kernel<<<dim3(NN / 32, BB), 512>>>(locals, localb);

    head_kernel<<<BB, 512>>>(g_w0, g_s0, g_b0, g_w1, g_s1, g_b1, outp);
}